// round 4
// baseline (speedup 1.0000x reference)
#include <cuda_runtime.h>
#include <cuda_bf16.h>
#include <cuda_fp16.h>
#include <math.h>

// Problem constants
#define NN   4096
#define FF   512
#define DD   64
#define HH   8
#define CC   40
#define MAXDEG 256

// ---------------- scratch (device globals; no allocation allowed) -----------
__device__ int   g_mode;                 // adj dtype: 0=f32 1=i32 2=u8 3=f64 4=bf16 5=f16
__device__ int   g_deg[NN];
__device__ int   g_nbr[NN * MAXDEG];                 // 4 MB
__device__ float g_h [HH * NN * DD];                 // 8 MB  [h][n][d]
__device__ float g_si[HH * NN];
__device__ float g_sj[HH * NN];
__device__ float g_x2[NN * FF];                      // 8 MB  [n][h*64+d]
__device__ float g_h2[NN * CC];
__device__ float g_tdst[NN];
__device__ float g_tsrc[NN];

// ---------------- adj dtype probe -------------------------------------------
__global__ void probe_kernel(const unsigned int* a) {
    unsigned w0 = a[0], w1 = a[1], wq = a[1024];
    int mode;
    if (w0 == 0x3F800000u)                      mode = 0;   // float32 (1.0f)
    else if (w0 == 0u && w1 == 0x3FF00000u)     mode = 3;   // float64 (1.0)
    else if ((w0 & 0xFFFFu) == 0x3F80u)         mode = 4;   // bf16 (1.0)
    else if ((w0 & 0xFFFFu) == 0x3C00u)         mode = 5;   // fp16 (1.0)
    else if (wq >= 256u)                        mode = 2;   // uint8/bool (diag byte 4097)
    else                                        mode = 1;   // int32
    g_mode = mode;
}

__device__ __forceinline__ bool adj_at(const void* adj, int mode, int idx) {
    switch (mode) {
        case 0:  return ((const float*)adj)[idx] != 0.f;
        case 1:  return ((const int*)adj)[idx] != 0;
        case 2:  return ((const unsigned char*)adj)[idx] != 0;
        case 3:  return ((const double*)adj)[idx] != 0.0;
        case 4:  return __bfloat162float(((const __nv_bfloat16*)adj)[idx]) != 0.f;
        default: return __half2float(((const __half*)adj)[idx]) != 0.f;
    }
}

// ---------------- edge-list build: one warp per row, deterministic order -----
__global__ void __launch_bounds__(256) build_edges_kernel(const void* adj) {
    int gw   = (blockIdx.x * 256 + threadIdx.x) >> 5;
    int lane = threadIdx.x & 31;
    if (gw >= NN) return;
    int mode = g_mode;
    int base = 0;
    int* nb  = g_nbr + gw * MAXDEG;
    int rowb = gw * NN;
    for (int c0 = 0; c0 < NN; c0 += 32) {
        int c = c0 + lane;
        bool on = adj_at(adj, mode, rowb + c);
        unsigned bal = __ballot_sync(0xFFFFFFFFu, on);
        if (on) {
            int pos = base + __popc(bal & ((1u << lane) - 1u));
            if (pos < MAXDEG) nb[pos] = c;
        }
        base += __popc(bal);
    }
    if (lane == 0) g_deg[gw] = base < MAXDEG ? base : MAXDEG;
}

// ---------------- GEMM1: h[h][n][d] = sum_f x[n][f] * W1[h][f][d] ------------
// 128x64 tile (full head width), BK=16, 256 threads, 8x4 per thread.
__global__ void __launch_bounds__(256) gemm1_kernel(const float* __restrict__ x,
                                                    const float* __restrict__ W1) {
    const int h  = blockIdx.y;
    const int n0 = blockIdx.x * 128;
    const float* B = W1 + h * FF * DD;     // [512][64]

    __shared__ float As[16][128];
    __shared__ float Bs[16][64];

    const int tid = threadIdx.x;
    const int tx = tid & 15;        // col group (d)
    const int ty = tid >> 4;        // row group (n)

    const int ar = tid >> 1;              // A row in tile (0..127)
    const int ac = (tid & 1) * 8;         // A col base (0 or 8)
    const int bkr = tid >> 4;             // B row (0..15)
    const int bc  = (tid & 15) * 4;       // B col base

    float acc[8][4];
#pragma unroll
    for (int i = 0; i < 8; i++)
#pragma unroll
        for (int j = 0; j < 4; j++) acc[i][j] = 0.f;

    for (int k0 = 0; k0 < FF; k0 += 16) {
        float4 a0 = *(const float4*)(x + (n0 + ar) * FF + k0 + ac);
        float4 a1 = *(const float4*)(x + (n0 + ar) * FF + k0 + ac + 4);
        As[ac + 0][ar] = a0.x; As[ac + 1][ar] = a0.y;
        As[ac + 2][ar] = a0.z; As[ac + 3][ar] = a0.w;
        As[ac + 4][ar] = a1.x; As[ac + 5][ar] = a1.y;
        As[ac + 6][ar] = a1.z; As[ac + 7][ar] = a1.w;
        *(float4*)&Bs[bkr][bc] = *(const float4*)(B + (k0 + bkr) * DD + bc);
        __syncthreads();

#pragma unroll
        for (int kk = 0; kk < 16; kk++) {
            float ra[8], rb[4];
#pragma unroll
            for (int i = 0; i < 8; i++) ra[i] = As[kk][ty * 8 + i];
#pragma unroll
            for (int j = 0; j < 4; j++) rb[j] = Bs[kk][tx * 4 + j];
#pragma unroll
            for (int i = 0; i < 8; i++)
#pragma unroll
                for (int j = 0; j < 4; j++) acc[i][j] += ra[i] * rb[j];
        }
        __syncthreads();
    }

    float* out = g_h + ((h << 12) + n0 + ty * 8) * DD + tx * 4;
#pragma unroll
    for (int i = 0; i < 8; i++) {
#pragma unroll
        for (int j = 0; j < 4; j++) out[i * DD + j] = acc[i][j];
    }
}

// ---------------- per-(h,n) attention scores si/sj ---------------------------
__global__ void __launch_bounds__(256) score1_kernel(const float* __restrict__ a1_src,
                                                     const float* __restrict__ a1_dst) {
    int gw   = (blockIdx.x * 256 + threadIdx.x) >> 5;
    int lane = threadIdx.x & 31;
    int h = gw >> 12;
    int n = gw & (NN - 1);
    const float* hp = g_h + ((h << 12) + n) * DD;
    float v0 = hp[lane], v1 = hp[lane + 32];
    float pd = v0 * a1_dst[h * DD + lane] + v1 * a1_dst[h * DD + lane + 32];
    float ps = v0 * a1_src[h * DD + lane] + v1 * a1_src[h * DD + lane + 32];
#pragma unroll
    for (int o = 16; o; o >>= 1) {
        pd += __shfl_xor_sync(0xFFFFFFFFu, pd, o);
        ps += __shfl_xor_sync(0xFFFFFFFFu, ps, o);
    }
    if (lane == 0) {
        g_si[(h << 12) + n] = pd;   // dst (i) term
        g_sj[(h << 12) + n] = ps;   // src (j) term
    }
}

// ---------------- layer-1 sparse attention + ELU -----------------------------
__global__ void __launch_bounds__(256) attn1_kernel() {
    int gw   = (blockIdx.x * 256 + threadIdx.x) >> 5;
    int lane = threadIdx.x & 31;
    int h = gw >> 12;
    int i = gw & (NN - 1);
    int deg = g_deg[i];
    const int* nb = g_nbr + i * MAXDEG;
    const float* sj = g_sj + (h << 12);
    float si = g_si[(h << 12) + i];

    float m = -3.0e38f;
    for (int t = lane; t < deg; t += 32) {
        float e = si + sj[nb[t]];
        e = e > 0.f ? e : 0.2f * e;
        m = fmaxf(m, e);
    }
#pragma unroll
    for (int o = 16; o; o >>= 1) m = fmaxf(m, __shfl_xor_sync(0xFFFFFFFFu, m, o));

    float s = 0.f;
    for (int t = lane; t < deg; t += 32) {
        float e = si + sj[nb[t]];
        e = e > 0.f ? e : 0.2f * e;
        s += __expf(e - m);
    }
#pragma unroll
    for (int o = 16; o; o >>= 1) s += __shfl_xor_sync(0xFFFFFFFFu, s, o);
    float inv = 1.f / s;

    const float* hb = g_h + (size_t)(h << 12) * DD;
    float a0 = 0.f, a1 = 0.f;
    for (int t = 0; t < deg; t++) {
        int j = nb[t];
        float e = si + sj[j];
        e = e > 0.f ? e : 0.2f * e;
        float w = __expf(e - m);
        const float* hj = hb + j * DD;
        a0 += w * hj[lane];
        a1 += w * hj[lane + 32];
    }
    a0 *= inv; a1 *= inv;
    a0 = a0 > 0.f ? a0 : expm1f(a0);   // ELU(alpha=1)
    a1 = a1 > 0.f ? a1 : expm1f(a1);
    g_x2[i * FF + h * DD + lane]      = a0;
    g_x2[i * FF + h * DD + lane + 32] = a1;
}

// ---------------- GEMM2 (h2 = x2 @ W2) + t_src/t_dst epilogue ----------------
__global__ void __launch_bounds__(64) gemm2_kernel(const float* __restrict__ W2,
                                                   const float* __restrict__ a2_src,
                                                   const float* __restrict__ a2_dst) {
    __shared__ float sx[FF];
    __shared__ float rd[64], rs[64];
    int n = blockIdx.x, tid = threadIdx.x;
    for (int f = tid; f < FF; f += 64) sx[f] = g_x2[n * FF + f];
    __syncthreads();
    float acc = 0.f;
    if (tid < CC) {
#pragma unroll 8
        for (int f = 0; f < FF; f++) acc += sx[f] * W2[f * CC + tid];
        g_h2[n * CC + tid] = acc;
    }
    rd[tid] = (tid < CC) ? acc * a2_dst[tid] : 0.f;
    rs[tid] = (tid < CC) ? acc * a2_src[tid] : 0.f;
    __syncthreads();
    for (int s2 = 32; s2 > 0; s2 >>= 1) {
        if (tid < s2) { rd[tid] += rd[tid + s2]; rs[tid] += rs[tid + s2]; }
        __syncthreads();
    }
    if (tid == 0) { g_tdst[n] = rd[0]; g_tsrc[n] = rs[0]; }
}

// ---------------- layer-2 sparse attention -> output -------------------------
__global__ void __launch_bounds__(256) attn2_kernel(float* __restrict__ out) {
    int i    = (blockIdx.x * 256 + threadIdx.x) >> 5;
    int lane = threadIdx.x & 31;
    int deg = g_deg[i];
    const int* nb = g_nbr + i * MAXDEG;
    float ti = g_tdst[i];

    float m = -3.0e38f;
    for (int t = lane; t < deg; t += 32) {
        float e = ti + g_tsrc[nb[t]];
        e = e > 0.f ? e : 0.2f * e;
        m = fmaxf(m, e);
    }
#pragma unroll
    for (int o = 16; o; o >>= 1) m = fmaxf(m, __shfl_xor_sync(0xFFFFFFFFu, m, o));

    float s = 0.f;
    for (int t = lane; t < deg; t += 32) {
        float e = ti + g_tsrc[nb[t]];
        e = e > 0.f ? e : 0.2f * e;
        s += __expf(e - m);
    }
#pragma unroll
    for (int o = 16; o; o >>= 1) s += __shfl_xor_sync(0xFFFFFFFFu, s, o);
    float inv = 1.f / s;

    float a0 = 0.f, a1 = 0.f;
    for (int t = 0; t < deg; t++) {
        int j = nb[t];
        float e = ti + g_tsrc[j];
        e = e > 0.f ? e : 0.2f * e;
        float w = __expf(e - m);
        a0 += w * g_h2[j * CC + lane];
        if (lane < CC - 32) a1 += w * g_h2[j * CC + 32 + lane];
    }
    out[i * CC + lane] = a0 * inv;
    if (lane < CC - 32) out[i * CC + 32 + lane] = a1 * inv;
}

// ---------------- launch ------------------------------------------------------
extern "C" void kernel_launch(void* const* d_in, const int* in_sizes, int n_in,
                              void* d_out, int out_size) {
    const float* x      = (const float*)d_in[0];
    const void*  adj    = d_in[1];
    const float* W1     = (const float*)d_in[2];
    const float* a1_src = (const float*)d_in[3];
    const float* a1_dst = (const float*)d_in[4];
    const float* W2     = (const float*)d_in[5];
    const float* a2_src = (const float*)d_in[6];
    const float* a2_dst = (const float*)d_in[7];
    float* out = (float*)d_out;

    probe_kernel<<<1, 1>>>((const unsigned int*)adj);
    build_edges_kernel<<<(NN / 8), 256>>>(adj);                 // 512 blocks
    gemm1_kernel<<<dim3(NN / 128, HH), 256>>>(x, W1);           // 32 x 8
    score1_kernel<<<(HH * NN) / 8, 256>>>(a1_src, a1_dst);      // 4096 blocks
    attn1_kernel<<<(HH * NN) / 8, 256>>>();                     // 4096 blocks
    gemm2_kernel<<<NN, 64>>>(W2, a2_src, a2_dst);               // 4096 blocks
    attn2_kernel<<<NN / 8, 256>>>(out);                         // 512 blocks
}

// round 6
// speedup vs baseline: 1.2216x; 1.2216x over previous
#include <cuda_runtime.h>
#include <cuda_bf16.h>
#include <cuda_fp16.h>
#include <math.h>
#include <cstdint>

// Problem constants
#define NN   4096
#define FF   512
#define DD   64
#define HH   8
#define CC   40
#define MAXDEG 256

// ---------------- scratch (device globals; no allocation allowed) -----------
__device__ int   g_mode;
__device__ int   g_deg[NN];
__device__ int   g_nbr[NN * MAXDEG];                 // 4 MB
__device__ float g_h [HH * NN * DD];                 // 8 MB  [h][n][d]
__device__ float g_si[HH * NN];
__device__ float g_sj[HH * NN];
__device__ float g_x2[NN * FF];                      // 8 MB
__device__ float g_h2[NN * CC];
__device__ float g_tdst[NN];
__device__ float g_tsrc[NN];
// bf16-split weights, transposed to [h][d][f]
__device__ uint4 g_wh[HH * DD * FF * 2 / 16];        // 512 KB
__device__ uint4 g_wl[HH * DD * FF * 2 / 16];        // 512 KB

// ---------------- small helpers ---------------------------------------------
__device__ __forceinline__ uint32_t smem_u32(const void* p) {
    uint32_t a;
    asm("{ .reg .u64 t; cvta.to.shared.u64 t, %1; cvt.u32.u64 %0, t; }" : "=r"(a) : "l"(p));
    return a;
}

__device__ __forceinline__ void ldmx4(uint32_t& r0, uint32_t& r1, uint32_t& r2,
                                      uint32_t& r3, uint32_t addr) {
    asm volatile("ldmatrix.sync.aligned.m8n8.x4.shared.b16 {%0,%1,%2,%3}, [%4];"
                 : "=r"(r0), "=r"(r1), "=r"(r2), "=r"(r3) : "r"(addr));
}

__device__ __forceinline__ void mma_bf16(float* c, const uint32_t* a,
                                         uint32_t b0, uint32_t b1) {
    asm volatile(
        "mma.sync.aligned.m16n8k16.row.col.f32.bf16.bf16.f32 "
        "{%0,%1,%2,%3}, {%4,%5,%6,%7}, {%8,%9}, {%0,%1,%2,%3};"
        : "+f"(c[0]), "+f"(c[1]), "+f"(c[2]), "+f"(c[3])
        : "r"(a[0]), "r"(a[1]), "r"(a[2]), "r"(a[3]), "r"(b0), "r"(b1));
}

__device__ __forceinline__ void split4(float4 v, uint2& hi, uint2& lo) {
    __nv_bfloat16 h0 = __float2bfloat16_rn(v.x), h1 = __float2bfloat16_rn(v.y);
    __nv_bfloat16 h2 = __float2bfloat16_rn(v.z), h3 = __float2bfloat16_rn(v.w);
    __nv_bfloat16 l0 = __float2bfloat16_rn(v.x - __bfloat162float(h0));
    __nv_bfloat16 l1 = __float2bfloat16_rn(v.y - __bfloat162float(h1));
    __nv_bfloat16 l2 = __float2bfloat16_rn(v.z - __bfloat162float(h2));
    __nv_bfloat16 l3 = __float2bfloat16_rn(v.w - __bfloat162float(h3));
    __nv_bfloat162 H0 = __halves2bfloat162(h0, h1), H1 = __halves2bfloat162(h2, h3);
    __nv_bfloat162 L0 = __halves2bfloat162(l0, l1), L1 = __halves2bfloat162(l2, l3);
    hi = make_uint2(*(uint32_t*)&H0, *(uint32_t*)&H1);
    lo = make_uint2(*(uint32_t*)&L0, *(uint32_t*)&L1);
}

// ---------------- adj dtype probe -------------------------------------------
__global__ void probe_kernel(const unsigned int* a) {
    unsigned w0 = a[0], w1 = a[1], wq = a[1024];
    int mode;
    if (w0 == 0x3F800000u)                      mode = 0;
    else if (w0 == 0u && w1 == 0x3FF00000u)     mode = 3;
    else if ((w0 & 0xFFFFu) == 0x3F80u)         mode = 4;
    else if ((w0 & 0xFFFFu) == 0x3C00u)         mode = 5;
    else if (wq >= 256u)                        mode = 2;
    else                                        mode = 1;
    g_mode = mode;
}

__device__ __forceinline__ bool adj_at(const void* adj, int mode, int idx) {
    switch (mode) {
        case 0:  return ((const float*)adj)[idx] != 0.f;
        case 1:  return ((const int*)adj)[idx] != 0;
        case 2:  return ((const unsigned char*)adj)[idx] != 0;
        case 3:  return ((const double*)adj)[idx] != 0.0;
        case 4:  return __bfloat162float(((const __nv_bfloat16*)adj)[idx]) != 0.f;
        default: return __half2float(((const __half*)adj)[idx]) != 0.f;
    }
}

// ---------------- edge-list build -------------------------------------------
__global__ void __launch_bounds__(256) build_edges_kernel(const void* adj) {
    int gw   = (blockIdx.x * 256 + threadIdx.x) >> 5;
    int lane = threadIdx.x & 31;
    if (gw >= NN) return;
    int mode = g_mode;
    int base = 0;
    int* nb  = g_nbr + gw * MAXDEG;
    int rowb = gw * NN;
    for (int c0 = 0; c0 < NN; c0 += 32) {
        int c = c0 + lane;
        bool on = adj_at(adj, mode, rowb + c);
        unsigned bal = __ballot_sync(0xFFFFFFFFu, on);
        if (on) {
            int pos = base + __popc(bal & ((1u << lane) - 1u));
            if (pos < MAXDEG) nb[pos] = c;
        }
        base += __popc(bal);
    }
    if (lane == 0) g_deg[gw] = base < MAXDEG ? base : MAXDEG;
}

// ---------------- convert + transpose W1 -> Wh/Wl bf16 [h][d][f] -------------
__global__ void __launch_bounds__(256) conv_w_kernel(const float* __restrict__ W1) {
    int idx = blockIdx.x * 256 + threadIdx.x;        // over HH*DD*FF
    int f = idx & (FF - 1);
    int d = (idx >> 9) & (DD - 1);
    int h = idx >> 15;
    float w = W1[h * (FF * DD) + f * DD + d];
    __nv_bfloat16 hi = __float2bfloat16_rn(w);
    __nv_bfloat16 lo = __float2bfloat16_rn(w - __bfloat162float(hi));
    ((__nv_bfloat16*)g_wh)[idx] = hi;
    ((__nv_bfloat16*)g_wl)[idx] = lo;
}

// ---------------- GEMM1 via mma.sync bf16 split, fused si/sj -----------------
// CTA tile 128(M) x 64(N), K = 512 in 16 chunks of 32.
// D = xh*Wh + xh*Wl + xl*Wh, fp32 accumulate.
__global__ void __launch_bounds__(256) gemm1_mma_kernel(const float* __restrict__ x,
                                                        const float* __restrict__ a1_src,
                                                        const float* __restrict__ a1_dst) {
    __shared__ __nv_bfloat16 s_ah[128 * 40], s_al[128 * 40];   // padded stride 40
    __shared__ __nv_bfloat16 s_bh[64 * 40],  s_bl[64 * 40];
    __shared__ float s_si[128], s_sj[128], s_adst[DD], s_asrc[DD];

    const int tid  = threadIdx.x;
    const int wid  = tid >> 5;
    const int lane = tid & 31;
    const int h    = blockIdx.y;
    const int n0   = blockIdx.x * 128;
    const int m_base = (wid >> 1) * 32;      // 4 M-groups
    const int n_base = (wid & 1) * 32;       // 2 N-groups

    if (tid < DD)              s_adst[tid]      = a1_dst[h * DD + tid];
    else if (tid < 2 * DD)     s_asrc[tid - DD] = a1_src[h * DD + tid - DD];
    if (tid < 128) { s_si[tid] = 0.f; s_sj[tid] = 0.f; }

    // loader mapping
    const int arow  = tid >> 1;            // 0..127
    const int ahalf = tid & 1;             // which 16-float half of the 32-float chunk
    const float* xrow = x + (size_t)(n0 + arow) * FF + ahalf * 16;
    const int brow  = (tid & 127) >> 1;    // 0..63
    const int bhalf = tid & 1;
    const __nv_bfloat16* wsrc =
        ((tid < 128) ? (const __nv_bfloat16*)g_wh : (const __nv_bfloat16*)g_wl)
        + (size_t)(h * DD + brow) * FF + bhalf * 16;
    __nv_bfloat16* bdst = ((tid < 128) ? s_bh : s_bl) + brow * 40 + bhalf * 16;
    __nv_bfloat16* adst_h = s_ah + arow * 40 + ahalf * 16;
    __nv_bfloat16* adst_l = s_al + arow * 40 + ahalf * 16;

    const uint32_t ah_base = smem_u32(s_ah);
    const uint32_t al_base = smem_u32(s_al);
    const uint32_t bh_base = smem_u32(s_bh);
    const uint32_t bl_base = smem_u32(s_bl);

    float acc[2][4][4];
#pragma unroll
    for (int mt = 0; mt < 2; mt++)
#pragma unroll
        for (int nt = 0; nt < 4; nt++)
#pragma unroll
            for (int q = 0; q < 4; q++) acc[mt][nt][q] = 0.f;

    // prefetch chunk 0
    float4 f0 = *(const float4*)(xrow + 0);
    float4 f1 = *(const float4*)(xrow + 4);
    float4 f2 = *(const float4*)(xrow + 8);
    float4 f3 = *(const float4*)(xrow + 12);
    uint4  w0 = *(const uint4*)(wsrc);
    uint4  w1 = *(const uint4*)(wsrc + 8);

    // ldmatrix lane addressing components
    const int lrow = lane & 15;
    const int lkb  = (lane >> 4) * 16;

    for (int c = 0; c < 16; c++) {
        // ---- convert & store to SMEM ----
        uint2 h0, l0, h1, l1, h2, l2, h3, l3;
        split4(f0, h0, l0); split4(f1, h1, l1);
        split4(f2, h2, l2); split4(f3, h3, l3);
        *(uint4*)(adst_h)     = make_uint4(h0.x, h0.y, h1.x, h1.y);
        *(uint4*)(adst_h + 8) = make_uint4(h2.x, h2.y, h3.x, h3.y);
        *(uint4*)(adst_l)     = make_uint4(l0.x, l0.y, l1.x, l1.y);
        *(uint4*)(adst_l + 8) = make_uint4(l2.x, l2.y, l3.x, l3.y);
        *(uint4*)(bdst)       = w0;
        *(uint4*)(bdst + 8)   = w1;
        __syncthreads();

        // ---- prefetch next chunk ----
        if (c < 15) {
            const float* xs = xrow + (c + 1) * 32;
            f0 = *(const float4*)(xs + 0);
            f1 = *(const float4*)(xs + 4);
            f2 = *(const float4*)(xs + 8);
            f3 = *(const float4*)(xs + 12);
            const __nv_bfloat16* ws = wsrc + (c + 1) * 32;
            w0 = *(const uint4*)(ws);
            w1 = *(const uint4*)(ws + 8);
        }

        // ---- compute: 2 k16 steps ----
#pragma unroll
        for (int ks = 0; ks < 2; ks++) {
            uint32_t fa_h[2][4], fa_l[2][4];
#pragma unroll
            for (int mt = 0; mt < 2; mt++) {
                uint32_t off = (uint32_t)(m_base + mt * 16 + lrow) * 80 + ks * 32 + lkb;
                ldmx4(fa_h[mt][0], fa_h[mt][1], fa_h[mt][2], fa_h[mt][3], ah_base + off);
                ldmx4(fa_l[mt][0], fa_l[mt][1], fa_l[mt][2], fa_l[mt][3], al_base + off);
            }
            uint32_t fb_h[4][2], fb_l[4][2];
#pragma unroll
            for (int bt = 0; bt < 2; bt++) {
                uint32_t off = (uint32_t)(n_base + bt * 16 + lrow) * 80 + ks * 32 + lkb;
                uint32_t q0, q1, q2, q3;
                ldmx4(q0, q1, q2, q3, bh_base + off);
                fb_h[bt * 2 + 0][0] = q0; fb_h[bt * 2 + 0][1] = q2;
                fb_h[bt * 2 + 1][0] = q1; fb_h[bt * 2 + 1][1] = q3;
                ldmx4(q0, q1, q2, q3, bl_base + off);
                fb_l[bt * 2 + 0][0] = q0; fb_l[bt * 2 + 0][1] = q2;
                fb_l[bt * 2 + 1][0] = q1; fb_l[bt * 2 + 1][1] = q3;
            }
#pragma unroll
            for (int mt = 0; mt < 2; mt++)
#pragma unroll
                for (int nt = 0; nt < 4; nt++) {
                    mma_bf16(acc[mt][nt], fa_h[mt], fb_h[nt][0], fb_h[nt][1]);
                    mma_bf16(acc[mt][nt], fa_h[mt], fb_l[nt][0], fb_l[nt][1]);
                    mma_bf16(acc[mt][nt], fa_l[mt], fb_h[nt][0], fb_h[nt][1]);
                }
        }
        __syncthreads();
    }

    // ---- epilogue: write g_h + fused si/sj ----
    const int grp = lane >> 2, qid = lane & 3;
#pragma unroll
    for (int mt = 0; mt < 2; mt++) {
        int r0 = m_base + mt * 16 + grp;
        float si0 = 0.f, sj0 = 0.f, si1 = 0.f, sj1 = 0.f;
#pragma unroll
        for (int nt = 0; nt < 4; nt++) {
            int cix = n_base + nt * 8 + qid * 2;
            float d00 = acc[mt][nt][0], d01 = acc[mt][nt][1];
            float d10 = acc[mt][nt][2], d11 = acc[mt][nt][3];
            float* hp = g_h + ((size_t)((h << 12) + n0 + r0)) * DD + cix;
            *(float2*)hp              = make_float2(d00, d01);
            *(float2*)(hp + 8 * DD)   = make_float2(d10, d11);
            si0 += d00 * s_adst[cix] + d01 * s_adst[cix + 1];
            sj0 += d00 * s_asrc[cix] + d01 * s_asrc[cix + 1];
            si1 += d10 * s_adst[cix] + d11 * s_adst[cix + 1];
            sj1 += d10 * s_asrc[cix] + d11 * s_asrc[cix + 1];
        }
#pragma unroll
        for (int o = 1; o <= 2; o <<= 1) {
            si0 += __shfl_xor_sync(0xFFFFFFFFu, si0, o);
            sj0 += __shfl_xor_sync(0xFFFFFFFFu, sj0, o);
            si1 += __shfl_xor_sync(0xFFFFFFFFu, si1, o);
            sj1 += __shfl_xor_sync(0xFFFFFFFFu, sj1, o);
        }
        if (qid == 0) {
            atomicAdd(&s_si[r0], si0);     atomicAdd(&s_sj[r0], sj0);
            atomicAdd(&s_si[r0 + 8], si1); atomicAdd(&s_sj[r0 + 8], sj1);
        }
    }
    __syncthreads();
    if (tid < 128) {
        g_si[(h << 12) + n0 + tid] = s_si[tid];
        g_sj[(h << 12) + n0 + tid] = s_sj[tid];
    }
}

// ---------------- layer-1 sparse attention + ELU -----------------------------
__global__ void __launch_bounds__(256) attn1_kernel() {
    int gw   = (blockIdx.x * 256 + threadIdx.x) >> 5;
    int lane = threadIdx.x & 31;
    int h = gw >> 12;
    int i = gw & (NN - 1);
    int deg = g_deg[i];
    const int* nb = g_nbr + i * MAXDEG;
    const float* sj = g_sj + (h << 12);
    float si = g_si[(h << 12) + i];

    float m = -3.0e38f;
    for (int t = lane; t < deg; t += 32) {
        float e = si + sj[nb[t]];
        e = e > 0.f ? e : 0.2f * e;
        m = fmaxf(m, e);
    }
#pragma unroll
    for (int o = 16; o; o >>= 1) m = fmaxf(m, __shfl_xor_sync(0xFFFFFFFFu, m, o));

    float s = 0.f;
    for (int t = lane; t < deg; t += 32) {
        float e = si + sj[nb[t]];
        e = e > 0.f ? e : 0.2f * e;
        s += __expf(e - m);
    }
#pragma unroll
    for (int o = 16; o; o >>= 1) s += __shfl_xor_sync(0xFFFFFFFFu, s, o);
    float inv = 1.f / s;

    const float* hb = g_h + (size_t)(h << 12) * DD;
    float a0 = 0.f, a1 = 0.f;
    for (int t = 0; t < deg; t++) {
        int j = nb[t];
        float e = si + sj[j];
        e = e > 0.f ? e : 0.2f * e;
        float w = __expf(e - m);
        const float* hj = hb + j * DD;
        a0 += w * hj[lane];
        a1 += w * hj[lane + 32];
    }
    a0 *= inv; a1 *= inv;
    a0 = a0 > 0.f ? a0 : expm1f(a0);
    a1 = a1 > 0.f ? a1 : expm1f(a1);
    g_x2[i * FF + h * DD + lane]      = a0;
    g_x2[i * FF + h * DD + lane + 32] = a1;
}

// ---------------- GEMM2 (h2 = x2 @ W2) + t_src/t_dst epilogue ----------------
__global__ void __launch_bounds__(64) gemm2_kernel(const float* __restrict__ W2,
                                                   const float* __restrict__ a2_src,
                                                   const float* __restrict__ a2_dst) {
    __shared__ float sx[FF];
    __shared__ float rd[64], rs[64];
    int n = blockIdx.x, tid = threadIdx.x;
    for (int f = tid; f < FF; f += 64) sx[f] = g_x2[n * FF + f];
    __syncthreads();
    float acc = 0.f;
    if (tid < CC) {
#pragma unroll 8
        for (int f = 0; f < FF; f++) acc += sx[f] * W2[f * CC + tid];
        g_h2[n * CC + tid] = acc;
    }
    rd[tid] = (tid < CC) ? acc * a2_dst[tid] : 0.f;
    rs[tid] = (tid < CC) ? acc * a2_src[tid] : 0.f;
    __syncthreads();
    for (int s2 = 32; s2 > 0; s2 >>= 1) {
        if (tid < s2) { rd[tid] += rd[tid + s2]; rs[tid] += rs[tid + s2]; }
        __syncthreads();
    }
    if (tid == 0) { g_tdst[n] = rd[0]; g_tsrc[n] = rs[0]; }
}

// ---------------- layer-2 sparse attention -> output -------------------------
__global__ void __launch_bounds__(256) attn2_kernel(float* __restrict__ out) {
    int i    = (blockIdx.x * 256 + threadIdx.x) >> 5;
    int lane = threadIdx.x & 31;
    int deg = g_deg[i];
    const int* nb = g_nbr + i * MAXDEG;
    float ti = g_tdst[i];

    float m = -3.0e38f;
    for (int t = lane; t < deg; t += 32) {
        float e = ti + g_tsrc[nb[t]];
        e = e > 0.f ? e : 0.2f * e;
        m = fmaxf(m, e);
    }
#pragma unroll
    for (int o = 16; o; o >>= 1) m = fmaxf(m, __shfl_xor_sync(0xFFFFFFFFu, m, o));

    float s = 0.f;
    for (int t = lane; t < deg; t += 32) {
        float e = ti + g_tsrc[nb[t]];
        e = e > 0.f ? e : 0.2f * e;
        s += __expf(e - m);
    }
#pragma unroll
    for (int o = 16; o; o >>= 1) s += __shfl_xor_sync(0xFFFFFFFFu, s, o);
    float inv = 1.f / s;

    float a0 = 0.f, a1 = 0.f;
    for (int t = 0; t < deg; t++) {
        int j = nb[t];
        float e = ti + g_tsrc[j];
        e = e > 0.f ? e : 0.2f * e;
        float w = __expf(e - m);
        a0 += w * g_h2[j * CC + lane];
        if (lane < CC - 32) a1 += w * g_h2[j * CC + 32 + lane];
    }
    out[i * CC + lane] = a0 * inv;
    if (lane < CC - 32) out[i * CC + 32 + lane] = a1 * inv;
}

// ---------------- launch ------------------------------------------------------
extern "C" void kernel_launch(void* const* d_in, const int* in_sizes, int n_in,
                              void* d_out, int out_size) {
    const float* x      = (const float*)d_in[0];
    const void*  adj    = d_in[1];
    const float* W1     = (const float*)d_in[2];
    const float* a1_src = (const float*)d_in[3];
    const float* a1_dst = (const float*)d_in[4];
    const float* W2     = (const float*)d_in[5];
    const float* a2_src = (const float*)d_in[6];
    const float* a2_dst = (const float*)d_in[7];
    float* out = (float*)d_out;

    probe_kernel<<<1, 1>>>((const unsigned int*)adj);
    build_edges_kernel<<<(NN / 8), 256>>>(adj);
    conv_w_kernel<<<(HH * DD * FF) / 256, 256>>>(W1);
    gemm1_mma_kernel<<<dim3(NN / 128, HH), 256>>>(x, a1_src, a1_dst);
    attn1_kernel<<<(HH * NN) / 8, 256>>>();
    gemm2_kernel<<<NN, 64>>>(W2, a2_src, a2_dst);
    attn2_kernel<<<NN / 8, 256>>>(out);
}